// round 14
// baseline (speedup 1.0000x reference)
#include <cuda_runtime.h>
#include <cuda_fp16.h>

#define NCHAN 256
#define NPTS  49

// fp16 HWC scratch for image 0 of levels 3..5 only, channel-interleaved:
// slot(pix, l, k) = pix*256 + 8*l + k  holds channel 32*k + l.  11 MB, L2-resident.
#define OFF_L3 0
#define OFF_L4 (16384 * 256)
#define OFF_L5 (OFF_L4 + 4096 * 256)
#define SCRATCH_ELEMS (OFF_L5 + 1024 * 256)
__device__ __align__(16) __half g_scratch[SCRATCH_ELEMS];

// ---- CHW(fp32) -> interleaved-HWC(fp16) transpose, levels 3,4,5 (672 blocks) ----
__global__ __launch_bounds__(512) void tpose35(const float* __restrict__ p3,
                                               const float* __restrict__ p4,
                                               const float* __restrict__ p5) {
    __shared__ float tile[256][33];
    int b = blockIdx.x;
    const float* in;
    __half* op;
    int HW;
    if (b < 512)      { in = p3; op = g_scratch + OFF_L3; HW = 16384; }
    else if (b < 640) { b -= 512; in = p4; op = g_scratch + OFF_L4; HW = 4096; }
    else              { b -= 640; in = p5; op = g_scratch + OFF_L5; HW = 1024; }

    int tx = threadIdx.x & 31, ty = threadIdx.x >> 5;  // 32 x 16
    int x = b * 32 + tx;
    #pragma unroll
    for (int j = ty; j < 256; j += 16)
        tile[j][tx] = __ldcs(in + j * HW + x);
    __syncthreads();

    int pbase = b * 32;
    #pragma unroll
    for (int px = ty; px < 32; px += 16) {
        __half2 h01 = __floats2half2_rn(tile[tx      ][px], tile[tx + 32 ][px]);
        __half2 h23 = __floats2half2_rn(tile[tx + 64 ][px], tile[tx + 96 ][px]);
        __half2 h45 = __floats2half2_rn(tile[tx + 128][px], tile[tx + 160][px]);
        __half2 h67 = __floats2half2_rn(tile[tx + 192][px], tile[tx + 224][px]);
        uint4 v;
        v.x = *(unsigned*)&h01;
        v.y = *(unsigned*)&h23;
        v.z = *(unsigned*)&h45;
        v.w = *(unsigned*)&h67;
        *(uint4*)(op + (pbase + px) * NCHAN + 8 * tx) = v;
    }
}

// setup helper: per-point sample params for a roi at level `level`
__device__ __forceinline__ void setup_pts(float rx1, float ry1, float rx2, float ry2,
                                          int W, int tid,
                                          int* oTL, int* oTR, int* oBL, int* oBR,
                                          float* slx, float* sly, float* sm) {
    if (tid < NPTS) {
        float scale = (float)(W - 1);
        float ny1 = ry1 * (1.0f / 1024.0f);
        float nx1 = rx1 * (1.0f / 1024.0f);
        float dy  = __fsub_rn(ry2 * (1.0f / 1024.0f), ny1);
        float dx  = __fsub_rn(rx2 * (1.0f / 1024.0f), nx1);

        int py = tid / 7;
        int px = tid - py * 7;

        float ty = (float)py / 6.0f;
        float ys = __fmul_rn(__fadd_rn(ny1, __fmul_rn(ty, dy)), scale);
        bool  vy = (ys >= 0.0f) && (ys <= scale);
        float ysc = fminf(fmaxf(ys, 0.0f), scale);
        int   y0  = (int)floorf(ysc);
        int   y1i = min(y0 + 1, W - 1);
        float ly  = __fsub_rn(ysc, (float)y0);

        float tx = (float)px / 6.0f;
        float xs = __fmul_rn(__fadd_rn(nx1, __fmul_rn(tx, dx)), scale);
        bool  vx = (xs >= 0.0f) && (xs <= scale);
        float xsc = fminf(fmaxf(xs, 0.0f), scale);
        int   x0  = (int)floorf(xsc);
        int   x1i = min(x0 + 1, W - 1);
        float lx  = __fsub_rn(xsc, (float)x0);

        oTL[tid] = y0  * W + x0;
        oTR[tid] = y0  * W + x1i;
        oBL[tid] = y1i * W + x0;
        oBR[tid] = y1i * W + x1i;
        slx[tid] = lx;
        sly[tid] = ly;
        sm[tid]  = (vy && vx) ? 1.0f : 0.0f;
    }
}

__device__ __forceinline__ int level_of(const float* rois, int n,
                                        float& rx1, float& ry1,
                                        float& rx2, float& ry2) {
    rx1 = __ldg(rois + 4 * n + 0);
    ry1 = __ldg(rois + 4 * n + 1);
    rx2 = __ldg(rois + 4 * n + 2);
    ry2 = __ldg(rois + 4 * n + 3);
    float area = (ry2 - ry1) * (rx2 - rx1);
    float lvlf = log2f(sqrtf(fmaxf(area, 0.0f)) / 224.0f);
    int level = (int)rintf(lvlf) + 4;          // half-even, matches jnp.round
    return min(5, max(2, level));
}

// ---- combined pool: blocks [0,nrois) = levels 3-5 fast path;
//      blocks [nrois, 9*nrois) = level-2 channel-slice blocks from NCHW p2 ----
__global__ __launch_bounds__(384, 3) void roi_pool(const float* __restrict__ p2,
                                                   const float* __restrict__ rois,
                                                   float* __restrict__ out,
                                                   int nrois) {
    __shared__ int   s_oTL[NPTS], s_oTR[NPTS], s_oBL[NPTS], s_oBR[NPTS];
    __shared__ float s_lx[NPTS], s_ly[NPTS], s_m[NPTS];

    int b   = blockIdx.x;
    int tid = threadIdx.x;

    if (b >= nrois) {
        // ===== level-2 slice: roi n, channels [32*slice, 32*slice+32) =====
        int idx = b - nrois;
        int n     = idx >> 3;
        int slice = idx & 7;

        float rx1, ry1, rx2, ry2;
        if (level_of(rois, n, rx1, ry1, rx2, ry2) != 2) return;

        const int W = 256;
        setup_pts(rx1, ry1, rx2, ry2, W, tid, s_oTL, s_oTR, s_oBL, s_oBR, s_lx, s_ly, s_m);
        __syncthreads();

        long obase = (long)n * (NCHAN * NPTS);
        int pt = tid & 63;   // 49 active
        int cg = tid >> 6;   // 0..5 (only 0..3 used)
        if (pt < NPTS && cg < 4) {
            int oTL = s_oTL[pt], oTR = s_oTR[pt], oBL = s_oBL[pt], oBR = s_oBR[pt];
            float lx = s_lx[pt], ly = s_ly[pt], m = s_m[pt];
            int cbase = 32 * slice + cg;
            #pragma unroll
            for (int i = 0; i < 8; i++) {          // c = cbase + 4*i
                const float* fc = p2 + (cbase + 4 * i) * 65536;
                float tl = __ldg(fc + oTL);
                float tr = __ldg(fc + oTR);
                float bl = __ldg(fc + oBL);
                float br = __ldg(fc + oBR);
                float top = fmaf(tr - tl, lx, tl);
                float bot = fmaf(br - bl, lx, bl);
                __stcs(&out[obase + (long)(cbase + 4 * i) * NPTS + pt],
                       fmaf(bot - top, ly, top) * m);
            }
        }
        return;
    }

    // ===== levels 3-5 roi: fp16 interleaved-HWC fast path =====
    int n = b;
    float rx1, ry1, rx2, ry2;
    int level = level_of(rois, n, rx1, ry1, rx2, ry2);
    if (level == 2) return;

    __shared__ __align__(16) float sout[NCHAN * NPTS];  // flat == output layout
    int W = 1024 >> level;

    setup_pts(rx1, ry1, rx2, ry2, W, tid, s_oTL, s_oTR, s_oBL, s_oBR, s_lx, s_ly, s_m);
    __syncthreads();

    long obase = (long)n * (NCHAN * NPTS);
    const __half* fm = g_scratch +
        ((level == 3) ? OFF_L3 : (level == 4) ? OFF_L4 : OFF_L5);
    int warpid = tid >> 5;       // 0..11, pts stride 12
    int lane   = tid & 31;
    int lbias  = 8 * lane;

    #pragma unroll 4
    for (int pt = warpid; pt < NPTS; pt += 12) {
        uint4 tlq = __ldg((const uint4*)(fm + s_oTL[pt] * NCHAN + lbias));
        uint4 trq = __ldg((const uint4*)(fm + s_oTR[pt] * NCHAN + lbias));
        uint4 blq = __ldg((const uint4*)(fm + s_oBL[pt] * NCHAN + lbias));
        uint4 brq = __ldg((const uint4*)(fm + s_oBR[pt] * NCHAN + lbias));
        float lx = s_lx[pt], ly = s_ly[pt], m = s_m[pt];

        const unsigned* tlw = (const unsigned*)&tlq;
        const unsigned* trw = (const unsigned*)&trq;
        const unsigned* blw = (const unsigned*)&blq;
        const unsigned* brw = (const unsigned*)&brq;
        #pragma unroll
        for (int j = 0; j < 4; j++) {          // half2 pair j -> k = 2j, 2j+1
            float2 tl = __half22float2(*(const __half2*)&tlw[j]);
            float2 tr = __half22float2(*(const __half2*)&trw[j]);
            float2 bl = __half22float2(*(const __half2*)&blw[j]);
            float2 br = __half22float2(*(const __half2*)&brw[j]);

            float topx = fmaf(tr.x - tl.x, lx, tl.x);
            float botx = fmaf(br.x - bl.x, lx, bl.x);
            sout[((2 * j) * 32 + lane) * NPTS + pt] = fmaf(botx - topx, ly, topx) * m;

            float topy = fmaf(tr.y - tl.y, lx, tl.y);
            float boty = fmaf(br.y - bl.y, lx, bl.y);
            sout[((2 * j + 1) * 32 + lane) * NPTS + pt] = fmaf(boty - topy, ly, topy) * m;
        }
    }
    __syncthreads();

    const float4* s4 = (const float4*)sout;
    float4* o4 = (float4*)(out + obase);
    for (int i = tid; i < NCHAN * NPTS / 4; i += 384)
        __stcs(o4 + i, s4[i]);
}

extern "C" void kernel_launch(void* const* d_in, const int* in_sizes, int n_in,
                              void* d_out, int out_size) {
    const float* p2   = (const float*)d_in[0];
    const float* p3   = (const float*)d_in[1];
    const float* p4   = (const float*)d_in[2];
    const float* p5   = (const float*)d_in[3];
    const float* rois = (const float*)d_in[4];
    float* out = (float*)d_out;

    int nrois = in_sizes[4] / 4;   // B*R

    tpose35<<<672, 512>>>(p3, p4, p5);
    roi_pool<<<9 * nrois, 384>>>(p2, rois, out, nrois);
}